// round 5
// baseline (speedup 1.0000x reference)
#include <cuda_runtime.h>
#include <math.h>

// Problem constants
#define N_    8
#define A_    16368
#define K_    200
#define B_    20
#define PIX   16384           // 128*128
#define G_    4               // k-values per main block (coeffs in registers)
#define GRP   (K_ / G_)       // 50
#define CH_   4               // pixel chunks per (n, k-group)
#define CHPIX (PIX / CH_)     // 4096
#define NB_MAIN (N_ * GRP * CH_)   // 1600
#define NB_Y    (N_ * 8)           // 64
#define NB_MISC (N_)               // 8
#define NPART   (NB_MAIN + NB_Y + NB_MISC)  // 1672
#define T1    256

__device__ float g_partials[NPART];
__device__ unsigned int g_count;   // zero-init; reset by final block each call

typedef unsigned long long u64;
#define ABS2 0x7fffffff7fffffffULL
#define SGN2 0x8000000080000000ULL

__device__ __forceinline__ float ex2f_(float x) {
    float r; asm("ex2.approx.ftz.f32 %0, %1;" : "=f"(r) : "f"(x)); return r;
}
__device__ __forceinline__ float lg2f_(float x) {
    float r; asm("lg2.approx.ftz.f32 %0, %1;" : "=f"(r) : "f"(x)); return r;
}
// packed f32x2 ops (Blackwell FFMA2 path — PTX-only)
__device__ __forceinline__ u64 fma2_(u64 a, u64 b, u64 c) {
    u64 r; asm("fma.rn.f32x2 %0, %1, %2, %3;" : "=l"(r) : "l"(a), "l"(b), "l"(c)); return r;
}
__device__ __forceinline__ u64 mul2_(u64 a, u64 b) {
    u64 r; asm("mul.rn.f32x2 %0, %1, %2;" : "=l"(r) : "l"(a), "l"(b)); return r;
}
__device__ __forceinline__ u64 add2_(u64 a, u64 b) {
    u64 r; asm("add.rn.f32x2 %0, %1, %2;" : "=l"(r) : "l"(a), "l"(b)); return r;
}
__device__ __forceinline__ void unpack2_(u64 v, float& a, float& b) {
    unsigned lo, hi;
    asm("mov.b64 {%0, %1}, %2;" : "=r"(lo), "=r"(hi) : "l"(v));
    a = __uint_as_float(lo); b = __uint_as_float(hi);
}
__device__ __forceinline__ u64 pack2_(float v) {
    u64 r; unsigned u = __float_as_uint(v);
    asm("mov.b64 %0, {%1, %2};" : "=l"(r) : "r"(u), "r"(u));
    return r;
}

#define LOG2E   1.4426950408889634f
#define LN2     0.6931471805599453f
#define LOG10_2 0.3010299956639812f
#define WM  (LN2 / ((float)PIX * (float)N_ * (float)K_))
#define WP  (1.0f / ((float)N_ * K_ * K_))
#define WN  (1.0f / ((float)N_ * 3.0f * K_ * K_))
#define WL  (1.0f / ((float)N_ * K_))

__global__ __launch_bounds__(T1, 3)
void allloss_kernel(const float* __restrict__ map_class,
                    const float* __restrict__ map_box,
                    const float* __restrict__ map_coef,
                    const float* __restrict__ proto,
                    const float* __restrict__ anchor_center,
                    const float* __restrict__ anchor_hw,
                    const float* __restrict__ gt_boxes,
                    const float* __restrict__ gt_masks,
                    const int*   __restrict__ pos_idx,
                    const int*   __restrict__ neg_idx,
                    const int*   __restrict__ gt_idx,
                    float*       __restrict__ out)
{
    const int bid = blockIdx.x;
    const int tid = threadIdx.x;

    __shared__ float  red[T1];
    __shared__ float  ck[K_][4];      // y blocks
    __shared__ int    bk[K_];
    __shared__ float  Cb[B_][4];
    __shared__ float  Ct[4];

    float partial = 0.0f;

    if (bid < NB_MAIN) {
        // ===== main mask term: sum of lg2(1+2^-|z|) + 0.5*|z|  (0.5*z handled in y-blocks) =====
        const int n   = bid / (GRP * CH_);
        const int rem = bid % (GRP * CH_);
        const int kg  = rem / CH_;
        const int ch  = rem % CH_;

        // 4 coefficient sets, packed {c,c}, in registers — NO shared traffic in hot loop
        u64 C0[G_], C1[G_], C2[G_], C3[G_];
#pragma unroll
        for (int k = 0; k < G_; ++k) {
            int a = pos_idx[n * K_ + kg * G_ + k];
            float4 cp = *(const float4*)(map_coef + ((size_t)n * A_ + a) * 4);
            C0[k] = pack2_(cp.x * LOG2E);
            C1[k] = pack2_(cp.y * LOG2E);
            C2[k] = pack2_(cp.z * LOG2E);
            C3[k] = pack2_(cp.w * LOG2E);
        }

        const float* pb = proto + (size_t)n * 4 * PIX;
        u64   accA   = 0ull;      // packed |z| accumulator
        float acc_lg = 0.0f;

#pragma unroll 1
        for (int it = 0; it < CHPIX / (T1 * 4); ++it) {    // 4 iterations, 4 pixels/thread
            int pix = ch * CHPIX + (it * T1 + tid) * 4;
            ulonglong2 q0 = *(const ulonglong2*)(pb + 0 * PIX + pix);
            ulonglong2 q1 = *(const ulonglong2*)(pb + 1 * PIX + pix);
            ulonglong2 q2 = *(const ulonglong2*)(pb + 2 * PIX + pix);
            ulonglong2 q3 = *(const ulonglong2*)(pb + 3 * PIX + pix);
#pragma unroll
            for (int kp = 0; kp < 2; ++kp) {     // k-pairs: (0,1), (2,3)
                float e[8];
#pragma unroll
                for (int j = 0; j < 2; ++j) {
                    int k = kp * 2 + j;
                    u64 za = fma2_(C0[k], q0.x, fma2_(C1[k], q1.x, fma2_(C2[k], q2.x, mul2_(C3[k], q3.x))));
                    u64 zb = fma2_(C0[k], q0.y, fma2_(C1[k], q1.y, fma2_(C2[k], q2.y, mul2_(C3[k], q3.y))));
                    u64 aa = za & ABS2;          // |z| pair
                    u64 ab = zb & ABS2;
                    u64 ma = za | SGN2;          // -|z| pair (EX2 input)
                    u64 mb = zb | SGN2;
                    accA = add2_(accA, aa);
                    accA = add2_(accA, ab);
                    float m0, m1, m2, m3;
                    unpack2_(ma, m0, m1);
                    unpack2_(mb, m2, m3);
                    e[j * 4 + 0] = ex2f_(m0);
                    e[j * 4 + 1] = ex2f_(m1);
                    e[j * 4 + 2] = ex2f_(m2);
                    e[j * 4 + 3] = ex2f_(m3);
                }
                // one LG2 per 8 elements: product of (1+e) in (1,2] each, <=256 total
                float v0 = (1.0f + e[0]) * (1.0f + e[1]);
                float v1 = (1.0f + e[2]) * (1.0f + e[3]);
                float v2 = (1.0f + e[4]) * (1.0f + e[5]);
                float v3 = (1.0f + e[6]) * (1.0f + e[7]);
                acc_lg += lg2f_((v0 * v1) * (v2 * v3));
            }
        }
        float ax, ay;
        unpack2_(accA, ax, ay);
        partial = (acc_lg + 0.5f * (ax + ay)) * WM;

    } else if (bid < NB_MAIN + NB_Y) {
        // ===== y-term and 0.5*Sum z term:  sum_pix [ 0.5*(Ctot.p) - sum_b y_b*(C_b.p) ] =====
        const int b2  = bid - NB_MAIN;
        const int n   = b2 >> 3;
        const int ch8 = b2 & 7;

        if (tid < K_) {
            int a = pos_idx[n * K_ + tid];
            const float* cp = map_coef + ((size_t)n * A_ + a) * 4;
            ck[tid][0] = cp[0] * LOG2E; ck[tid][1] = cp[1] * LOG2E;
            ck[tid][2] = cp[2] * LOG2E; ck[tid][3] = cp[3] * LOG2E;
            bk[tid] = gt_idx[n * K_ + tid];
        }
        __syncthreads();
        if (tid < B_ * 4) {
            int b = tid >> 2, j = tid & 3;
            float s = 0.0f;
            for (int k = 0; k < K_; ++k)
                if (bk[k] == b) s += ck[k][j];
            Cb[b][j] = s;
        }
        __syncthreads();
        if (tid < 4) {
            float s = 0.0f;
            for (int b = 0; b < B_; ++b) s += Cb[b][tid];
            Ct[tid] = s;
        }
        __syncthreads();

        const float* pb = proto + (size_t)n * 4 * PIX;
        const float* gm = gt_masks + (size_t)n * B_ * PIX;
        float accD = 0.0f, accE = 0.0f;
#pragma unroll 1
        for (int it = 0; it < 2; ++it) {
            int pix = ch8 * 2048 + (it * T1 + tid) * 4;
            float4 p0 = *(const float4*)(pb + 0 * PIX + pix);
            float4 p1 = *(const float4*)(pb + 1 * PIX + pix);
            float4 p2 = *(const float4*)(pb + 2 * PIX + pix);
            float4 p3 = *(const float4*)(pb + 3 * PIX + pix);
            float t0 = Ct[0], t1 = Ct[1], t2 = Ct[2], t3 = Ct[3];
            accE += fmaf(t0, p0.x, fmaf(t1, p1.x, fmaf(t2, p2.x, t3 * p3.x)));
            accE += fmaf(t0, p0.y, fmaf(t1, p1.y, fmaf(t2, p2.y, t3 * p3.y)));
            accE += fmaf(t0, p0.z, fmaf(t1, p1.z, fmaf(t2, p2.z, t3 * p3.z)));
            accE += fmaf(t0, p0.w, fmaf(t1, p1.w, fmaf(t2, p2.w, t3 * p3.w)));
#pragma unroll
            for (int b = 0; b < B_; ++b) {
                float4 y = *(const float4*)(gm + (size_t)b * PIX + pix);
                float cb0 = Cb[b][0], cb1 = Cb[b][1], cb2 = Cb[b][2], cb3 = Cb[b][3];
                float Zx = fmaf(cb0, p0.x, fmaf(cb1, p1.x, fmaf(cb2, p2.x, cb3 * p3.x)));
                float Zy = fmaf(cb0, p0.y, fmaf(cb1, p1.y, fmaf(cb2, p2.y, cb3 * p3.y)));
                float Zz = fmaf(cb0, p0.z, fmaf(cb1, p1.z, fmaf(cb2, p2.z, cb3 * p3.z)));
                float Zw = fmaf(cb0, p0.w, fmaf(cb1, p1.w, fmaf(cb2, p2.w, cb3 * p3.w)));
                accD = fmaf(y.x, Zx, accD);
                accD = fmaf(y.y, Zy, accD);
                accD = fmaf(y.z, Zz, accD);
                accD = fmaf(y.w, Zw, accD);
            }
        }
        partial = (0.5f * accE - accD) * WM;

    } else {
        // ===== cls (pos+neg) + loc for one image =====
        const int n = bid - NB_MAIN - NB_Y;
        const float EPS = 1e-7f;
        float s = 0.0f;

        if (tid < K_) {
            int a = pos_idx[n * K_ + tid];
            float p = map_class[n * A_ + a];
            p = fminf(fmaxf(p, EPS), 1.0f - EPS);
            s += -lg2f_(p) * (LN2 * WP);

            int gi = gt_idx[n * K_ + tid];
            const float* pr = map_box + ((size_t)n * A_ + a) * 4;
            const float* gt = gt_boxes + ((size_t)n * B_ + gi) * 4;
            float ac0 = anchor_center[a * 2 + 0];
            float ac1 = anchor_center[a * 2 + 1];
            float ah  = anchor_hw[a * 2 + 0];
            float aw  = anchor_hw[a * 2 + 1];
            float t0 = (gt[0] - ac0) / ah;
            float t1 = (gt[1] - ac1) / aw;
            float t2 = lg2f_(gt[2] / ah) * LOG10_2;
            float t3 = lg2f_(gt[3] / aw) * LOG10_2;
            float d, ad, l = 0.0f;
            d = pr[0] - t0; ad = fabsf(d); l += (ad < 1.0f) ? 0.5f * d * d : ad - 0.5f;
            d = pr[1] - t1; ad = fabsf(d); l += (ad < 1.0f) ? 0.5f * d * d : ad - 0.5f;
            d = pr[2] - t2; ad = fabsf(d); l += (ad < 1.0f) ? 0.5f * d * d : ad - 0.5f;
            d = pr[3] - t3; ad = fabsf(d); l += (ad < 1.0f) ? 0.5f * d * d : ad - 0.5f;
            s += l * WL;
        }
        for (int i = tid; i < 3 * K_; i += T1) {
            int a = neg_idx[n * 3 * K_ + i];
            float p = map_class[n * A_ + a];
            p = fminf(fmaxf(p, EPS), 1.0f - EPS);
            s += -lg2f_(1.0f - p) * (LN2 * WN);
        }
        partial = s;
    }

    // ===== block reduction =====
    red[tid] = partial;
    __syncthreads();
#pragma unroll
    for (int st = T1 / 2; st > 0; st >>= 1) {
        if (tid < st) red[tid] += red[tid + st];
        __syncthreads();
    }
    if (tid == 0) g_partials[bid] = red[0];

    // ===== last-block final reduction =====
    __shared__ bool isLast;
    if (tid == 0) {
        __threadfence();
        unsigned int old = atomicAdd(&g_count, 1u);
        isLast = (old == NPART - 1);
    }
    __syncthreads();
    if (isLast) {
        float s = 0.0f;
        for (int i = tid; i < NPART; i += T1) s += g_partials[i];
        red[tid] = s;
        __syncthreads();
#pragma unroll
        for (int st = T1 / 2; st > 0; st >>= 1) {
            if (tid < st) red[tid] += red[tid + st];
            __syncthreads();
        }
        if (tid == 0) {
            out[0] = red[0];
            g_count = 0;
        }
    }
}

extern "C" void kernel_launch(void* const* d_in, const int* in_sizes, int n_in,
                              void* d_out, int out_size)
{
    const float* map_class     = (const float*)d_in[0];
    const float* map_box       = (const float*)d_in[1];
    const float* map_coef      = (const float*)d_in[2];
    const float* proto         = (const float*)d_in[3];
    const float* anchor_center = (const float*)d_in[4];
    const float* anchor_hw     = (const float*)d_in[5];
    const float* gt_boxes      = (const float*)d_in[6];
    const float* gt_masks      = (const float*)d_in[7];
    const int*   pos_idx       = (const int*)d_in[8];
    const int*   neg_idx       = (const int*)d_in[9];
    const int*   gt_idx        = (const int*)d_in[10];
    float* out = (float*)d_out;

    allloss_kernel<<<NPART, T1>>>(map_class, map_box, map_coef, proto,
                                  anchor_center, anchor_hw, gt_boxes, gt_masks,
                                  pos_idx, neg_idx, gt_idx, out);
}

// round 6
// speedup vs baseline: 1.3845x; 1.3845x over previous
#include <cuda_runtime.h>
#include <math.h>

// Problem constants
#define N_    8
#define A_    16368
#define K_    200
#define B_    20
#define PIX   16384           // 128*128
#define G_    8               // k-values per main block (4 packed k-pairs in regs)
#define GRP   (K_ / G_)       // 25
#define CH_   4               // pixel chunks per (n, k-group)
#define CHPIX (PIX / CH_)     // 4096
#define NB_MAIN (N_ * GRP * CH_)   // 800
#define NB_Y    (N_ * 8)           // 64
#define NB_MISC (N_)               // 8
#define NPART   (NB_MAIN + NB_Y + NB_MISC)  // 872
#define T1    256

__device__ float g_partials[NPART];
__device__ unsigned int g_count;   // zero-init; reset by final block each call

typedef unsigned long long u64;
#define SGN2 0x8000000080000000ULL

__device__ __forceinline__ float ex2f_(float x) {
    float r; asm("ex2.approx.ftz.f32 %0, %1;" : "=f"(r) : "f"(x)); return r;
}
__device__ __forceinline__ float lg2f_(float x) {
    float r; asm("lg2.approx.ftz.f32 %0, %1;" : "=f"(r) : "f"(x)); return r;
}
// packed f32x2 ops (Blackwell FFMA2 path — PTX-only)
__device__ __forceinline__ u64 fma2_(u64 a, u64 b, u64 c) {
    u64 r; asm("fma.rn.f32x2 %0, %1, %2, %3;" : "=l"(r) : "l"(a), "l"(b), "l"(c)); return r;
}
__device__ __forceinline__ u64 mul2_(u64 a, u64 b) {
    u64 r; asm("mul.rn.f32x2 %0, %1, %2;" : "=l"(r) : "l"(a), "l"(b)); return r;
}
__device__ __forceinline__ u64 add2_(u64 a, u64 b) {
    u64 r; asm("add.rn.f32x2 %0, %1, %2;" : "=l"(r) : "l"(a), "l"(b)); return r;
}
__device__ __forceinline__ void unpack2_(u64 v, float& a, float& b) {
    unsigned lo, hi;
    asm("mov.b64 {%0, %1}, %2;" : "=r"(lo), "=r"(hi) : "l"(v));
    a = __uint_as_float(lo); b = __uint_as_float(hi);
}
__device__ __forceinline__ u64 pack2s_(float x, float y) {
    u64 r; unsigned ux = __float_as_uint(x), uy = __float_as_uint(y);
    asm("mov.b64 %0, {%1, %2};" : "=l"(r) : "r"(ux), "r"(uy));
    return r;
}
__device__ __forceinline__ u64 bcast2_(float v) {
    return pack2s_(v, v);
}

#define LOG2E   1.4426950408889634f
#define LN2     0.6931471805599453f
#define LOG10_2 0.3010299956639812f
#define WM  (LN2 / ((float)PIX * (float)N_ * (float)K_))
#define WP  (1.0f / ((float)N_ * K_ * K_))
#define WN  (1.0f / ((float)N_ * 3.0f * K_ * K_))
#define WL  (1.0f / ((float)N_ * K_))

__global__ __launch_bounds__(T1, 3)
void allloss_kernel(const float* __restrict__ map_class,
                    const float* __restrict__ map_box,
                    const float* __restrict__ map_coef,
                    const float* __restrict__ proto,
                    const float* __restrict__ anchor_center,
                    const float* __restrict__ anchor_hw,
                    const float* __restrict__ gt_boxes,
                    const float* __restrict__ gt_masks,
                    const int*   __restrict__ pos_idx,
                    const int*   __restrict__ neg_idx,
                    const int*   __restrict__ gt_idx,
                    float*       __restrict__ out)
{
    const int bid = blockIdx.x;
    const int tid = threadIdx.x;

    __shared__ float  red[T1];
    __shared__ float  ck[K_][4];      // y blocks
    __shared__ int    bk[K_];
    __shared__ float  Cb[B_][4];
    __shared__ float  Ct[4];

    float partial = 0.0f;

    if (bid < NB_MAIN) {
        // ===== main mask term: sum of lg2(1+2^-|z|) + 0.5*|z|  (0.5*z in y-blocks) =====
        const int n   = bid / (GRP * CH_);
        const int rem = bid % (GRP * CH_);
        const int kg  = rem / CH_;
        const int ch  = rem % CH_;

        // 8 coefficient sets as 4 k-pairs, packed over k: C[j][kp] = {c_{2kp}[j], c_{2kp+1}[j]}
        u64 C0[4], C1[4], C2[4], C3[4];
#pragma unroll
        for (int kp = 0; kp < 4; ++kp) {
            int a0 = pos_idx[n * K_ + kg * G_ + kp * 2 + 0];
            int a1 = pos_idx[n * K_ + kg * G_ + kp * 2 + 1];
            float4 ca = *(const float4*)(map_coef + ((size_t)n * A_ + a0) * 4);
            float4 cb = *(const float4*)(map_coef + ((size_t)n * A_ + a1) * 4);
            C0[kp] = pack2s_(ca.x * LOG2E, cb.x * LOG2E);
            C1[kp] = pack2s_(ca.y * LOG2E, cb.y * LOG2E);
            C2[kp] = pack2s_(ca.z * LOG2E, cb.z * LOG2E);
            C3[kp] = pack2s_(ca.w * LOG2E, cb.w * LOG2E);
        }

        const float* pb = proto + (size_t)n * 4 * PIX;
        u64   accM0 = 0ull, accM1 = 0ull;   // packed sum of -|z|
        float acc_lg = 0.0f;

#pragma unroll 1
        for (int it = 0; it < CHPIX / (T1 * 4); ++it) {    // 4 iterations, 4 pixels/thread
            int pix = ch * CHPIX + (it * T1 + tid) * 4;
            float4 p0 = *(const float4*)(pb + 0 * PIX + pix);
            float4 p1 = *(const float4*)(pb + 1 * PIX + pix);
            float4 p2 = *(const float4*)(pb + 2 * PIX + pix);
            float4 p3 = *(const float4*)(pb + 3 * PIX + pix);
            const float* f0 = &p0.x;
            const float* f1 = &p1.x;
            const float* f2 = &p2.x;
            const float* f3 = &p3.x;
#pragma unroll
            for (int j = 0; j < 4; ++j) {      // pixels
                u64 P0 = bcast2_(f0[j]);
                u64 P1 = bcast2_(f1[j]);
                u64 P2 = bcast2_(f2[j]);
                u64 P3 = bcast2_(f3[j]);
                float e[8];
#pragma unroll
                for (int kp = 0; kp < 4; ++kp) {
                    u64 z = fma2_(C0[kp], P0, fma2_(C1[kp], P1, fma2_(C2[kp], P2, mul2_(C3[kp], P3))));
                    u64 m = z | SGN2;           // packed -|z|
                    if (kp & 1) accM1 = add2_(accM1, m);
                    else        accM0 = add2_(accM0, m);
                    float m0, m1;
                    unpack2_(m, m0, m1);
                    e[kp * 2 + 0] = ex2f_(m0);
                    e[kp * 2 + 1] = ex2f_(m1);
                }
                // one LG2 per 8 elements: each (1+e) in (1,2], product <= 256
                float v0 = (1.0f + e[0]) * (1.0f + e[1]);
                float v1 = (1.0f + e[2]) * (1.0f + e[3]);
                float v2 = (1.0f + e[4]) * (1.0f + e[5]);
                float v3 = (1.0f + e[6]) * (1.0f + e[7]);
                acc_lg += lg2f_((v0 * v1) * (v2 * v3));
            }
        }
        u64 accM = add2_(accM0, accM1);
        float mx, my;
        unpack2_(accM, mx, my);
        // Sum|z| = -(mx+my)
        partial = (acc_lg - 0.5f * (mx + my)) * WM;

    } else if (bid < NB_MAIN + NB_Y) {
        // ===== y-term and 0.5*Sum z term:  sum_pix [ 0.5*(Ctot.p) - sum_b y_b*(C_b.p) ] =====
        const int b2  = bid - NB_MAIN;
        const int n   = b2 >> 3;
        const int ch8 = b2 & 7;

        if (tid < K_) {
            int a = pos_idx[n * K_ + tid];
            const float* cp = map_coef + ((size_t)n * A_ + a) * 4;
            ck[tid][0] = cp[0] * LOG2E; ck[tid][1] = cp[1] * LOG2E;
            ck[tid][2] = cp[2] * LOG2E; ck[tid][3] = cp[3] * LOG2E;
            bk[tid] = gt_idx[n * K_ + tid];
        }
        __syncthreads();
        if (tid < B_ * 4) {
            int b = tid >> 2, j = tid & 3;
            float s = 0.0f;
            for (int k = 0; k < K_; ++k)
                if (bk[k] == b) s += ck[k][j];
            Cb[b][j] = s;
        }
        __syncthreads();
        if (tid < 4) {
            float s = 0.0f;
            for (int b = 0; b < B_; ++b) s += Cb[b][tid];
            Ct[tid] = s;
        }
        __syncthreads();

        const float* pb = proto + (size_t)n * 4 * PIX;
        const float* gm = gt_masks + (size_t)n * B_ * PIX;
        float accD = 0.0f, accE = 0.0f;
#pragma unroll 1
        for (int it = 0; it < 2; ++it) {
            int pix = ch8 * 2048 + (it * T1 + tid) * 4;
            float4 p0 = *(const float4*)(pb + 0 * PIX + pix);
            float4 p1 = *(const float4*)(pb + 1 * PIX + pix);
            float4 p2 = *(const float4*)(pb + 2 * PIX + pix);
            float4 p3 = *(const float4*)(pb + 3 * PIX + pix);
            float t0 = Ct[0], t1 = Ct[1], t2 = Ct[2], t3 = Ct[3];
            accE += fmaf(t0, p0.x, fmaf(t1, p1.x, fmaf(t2, p2.x, t3 * p3.x)));
            accE += fmaf(t0, p0.y, fmaf(t1, p1.y, fmaf(t2, p2.y, t3 * p3.y)));
            accE += fmaf(t0, p0.z, fmaf(t1, p1.z, fmaf(t2, p2.z, t3 * p3.z)));
            accE += fmaf(t0, p0.w, fmaf(t1, p1.w, fmaf(t2, p2.w, t3 * p3.w)));
#pragma unroll
            for (int b = 0; b < B_; ++b) {
                float4 y = *(const float4*)(gm + (size_t)b * PIX + pix);
                float cb0 = Cb[b][0], cb1 = Cb[b][1], cb2 = Cb[b][2], cb3 = Cb[b][3];
                float Zx = fmaf(cb0, p0.x, fmaf(cb1, p1.x, fmaf(cb2, p2.x, cb3 * p3.x)));
                float Zy = fmaf(cb0, p0.y, fmaf(cb1, p1.y, fmaf(cb2, p2.y, cb3 * p3.y)));
                float Zz = fmaf(cb0, p0.z, fmaf(cb1, p1.z, fmaf(cb2, p2.z, cb3 * p3.z)));
                float Zw = fmaf(cb0, p0.w, fmaf(cb1, p1.w, fmaf(cb2, p2.w, cb3 * p3.w)));
                accD = fmaf(y.x, Zx, accD);
                accD = fmaf(y.y, Zy, accD);
                accD = fmaf(y.z, Zz, accD);
                accD = fmaf(y.w, Zw, accD);
            }
        }
        partial = (0.5f * accE - accD) * WM;

    } else {
        // ===== cls (pos+neg) + loc for one image =====
        const int n = bid - NB_MAIN - NB_Y;
        const float EPS = 1e-7f;
        float s = 0.0f;

        if (tid < K_) {
            int a = pos_idx[n * K_ + tid];
            float p = map_class[n * A_ + a];
            p = fminf(fmaxf(p, EPS), 1.0f - EPS);
            s += -lg2f_(p) * (LN2 * WP);

            int gi = gt_idx[n * K_ + tid];
            const float* pr = map_box + ((size_t)n * A_ + a) * 4;
            const float* gt = gt_boxes + ((size_t)n * B_ + gi) * 4;
            float ac0 = anchor_center[a * 2 + 0];
            float ac1 = anchor_center[a * 2 + 1];
            float ah  = anchor_hw[a * 2 + 0];
            float aw  = anchor_hw[a * 2 + 1];
            float t0 = (gt[0] - ac0) / ah;
            float t1 = (gt[1] - ac1) / aw;
            float t2 = lg2f_(gt[2] / ah) * LOG10_2;
            float t3 = lg2f_(gt[3] / aw) * LOG10_2;
            float d, ad, l = 0.0f;
            d = pr[0] - t0; ad = fabsf(d); l += (ad < 1.0f) ? 0.5f * d * d : ad - 0.5f;
            d = pr[1] - t1; ad = fabsf(d); l += (ad < 1.0f) ? 0.5f * d * d : ad - 0.5f;
            d = pr[2] - t2; ad = fabsf(d); l += (ad < 1.0f) ? 0.5f * d * d : ad - 0.5f;
            d = pr[3] - t3; ad = fabsf(d); l += (ad < 1.0f) ? 0.5f * d * d : ad - 0.5f;
            s += l * WL;
        }
        for (int i = tid; i < 3 * K_; i += T1) {
            int a = neg_idx[n * 3 * K_ + i];
            float p = map_class[n * A_ + a];
            p = fminf(fmaxf(p, EPS), 1.0f - EPS);
            s += -lg2f_(1.0f - p) * (LN2 * WN);
        }
        partial = s;
    }

    // ===== block reduction =====
    red[tid] = partial;
    __syncthreads();
#pragma unroll
    for (int st = T1 / 2; st > 0; st >>= 1) {
        if (tid < st) red[tid] += red[tid + st];
        __syncthreads();
    }
    if (tid == 0) g_partials[bid] = red[0];

    // ===== last-block final reduction =====
    __shared__ bool isLast;
    if (tid == 0) {
        __threadfence();
        unsigned int old = atomicAdd(&g_count, 1u);
        isLast = (old == NPART - 1);
    }
    __syncthreads();
    if (isLast) {
        float s = 0.0f;
        for (int i = tid; i < NPART; i += T1) s += g_partials[i];
        red[tid] = s;
        __syncthreads();
#pragma unroll
        for (int st = T1 / 2; st > 0; st >>= 1) {
            if (tid < st) red[tid] += red[tid + st];
            __syncthreads();
        }
        if (tid == 0) {
            out[0] = red[0];
            g_count = 0;
        }
    }
}

extern "C" void kernel_launch(void* const* d_in, const int* in_sizes, int n_in,
                              void* d_out, int out_size)
{
    const float* map_class     = (const float*)d_in[0];
    const float* map_box       = (const float*)d_in[1];
    const float* map_coef      = (const float*)d_in[2];
    const float* proto         = (const float*)d_in[3];
    const float* anchor_center = (const float*)d_in[4];
    const float* anchor_hw     = (const float*)d_in[5];
    const float* gt_boxes      = (const float*)d_in[6];
    const float* gt_masks      = (const float*)d_in[7];
    const int*   pos_idx       = (const int*)d_in[8];
    const int*   neg_idx       = (const int*)d_in[9];
    const int*   gt_idx        = (const int*)d_in[10];
    float* out = (float*)d_out;

    allloss_kernel<<<NPART, T1>>>(map_class, map_box, map_coef, proto,
                                  anchor_center, anchor_hw, gt_boxes, gt_masks,
                                  pos_idx, neg_idx, gt_idx, out);
}